// round 3
// baseline (speedup 1.0000x reference)
#include <cuda_runtime.h>
#include <cfloat>

// Problem constants (fixed by the reference setup_inputs)
#define B_    8
#define S_    4094
#define NH_   8
#define HD_   64
#define W_    63        // half window; full window = 127

// Tiling
#define TQ      64      // queries per CTA
#define NK      192     // padded key rows per CTA (actual 190 = TQ + 2*W)
#define NCHUNK  64      // ceil(4094/64)

// Shared-memory strides (floats) — chosen for conflict-free transposed fills
#define SQT_STRIDE 65
#define SKT_STRIDE 193
#define SV_STRIDE  64
#define SPT_STRIDE 65

// Shared-memory layout (float offsets)
#define OFF_QT 0
#define OFF_KT (HD_ * SQT_STRIDE)                 // 4160
#define OFF_V  (OFF_KT + HD_ * SKT_STRIDE)        // 16512
#define OFF_PT (OFF_V + NK * SV_STRIDE)           // 28800
#define SMEM_FLOATS (OFF_PT + NK * SPT_STRIDE)    // 41280 floats = 165120 B

__global__ __launch_bounds__(256, 1)
void window_attn_kernel(const float* __restrict__ qg,
                        const float* __restrict__ kg,
                        const float* __restrict__ vg,
                        float* __restrict__ og)
{
    extern __shared__ float sm[];
    float* sQT = sm + OFF_QT;   // [d][q]   Q transposed, pre-scaled by 1/8
    float* sKT = sm + OFF_KT;   // [d][r]   K transposed (zero for OOB rows)
    float* sV  = sm + OFF_V;    // [r][d]   V (zero for OOB rows)
    float* sPT = sm + OFF_PT;   // [r][q]   unnormalized softmax probs

    const int bx    = blockIdx.x;
    const int chunk = bx & (NCHUNK - 1);
    const int head  = (bx >> 6) & (NH_ - 1);
    const int batch = bx >> 9;
    const int t0    = chunk * TQ;

    const int tid = threadIdx.x;
    const int tx  = tid & 15;      // key-col group / dim group
    const int ty  = tid >> 4;      // query-row group
    const int q0  = ty << 2;       // first of 4 query rows owned by this thread

    // ---- Fill Q (transposed, scaled). Coalesced gmem reads; smem writes
    // hit consecutive banks (stride 65). Queries past S contribute nothing
    // (stores are guarded at the end).
    for (int idx = tid; idx < TQ * HD_; idx += 256) {
        int ql = idx >> 6, d = idx & 63;
        int t = t0 + ql;
        float v = 0.f;
        if (t < S_)
            v = qg[((size_t)(batch * S_ + t) * NH_ + head) * HD_ + d] * 0.125f;
        sQT[d * SQT_STRIDE + ql] = v;
    }

    // ---- Fill K (transposed) and V. Rows whose global position falls
    // outside [0, S) are ZERO — this reproduces the reference's zero-padded
    // K/V (score 0 inside the band, value 0), which the reference softmax
    // includes in the denominator.
    for (int idx = tid; idx < NK * HD_; idx += 256) {
        int r = idx >> 6, d = idx & 63;
        int g = t0 - W_ + r;
        float kv = 0.f, vv = 0.f;
        if (g >= 0 && g < S_) {
            size_t off = ((size_t)(batch * S_ + g) * NH_ + head) * HD_ + d;
            kv = kg[off];
            vv = vg[off];
        }
        sKT[d * SKT_STRIDE + r] = kv;
        sV[r * SV_STRIDE + d]   = vv;
    }
    __syncthreads();

    // ---- GEMM1: scores S[64][192] = Q @ K^T. Thread tile 4q x 12n,
    // n = tx + 16*j. A loads broadcast within warp (2 distinct ty),
    // B loads conflict-free (consecutive tx → consecutive floats).
    float acc[4][12];
    #pragma unroll
    for (int i = 0; i < 4; ++i)
        #pragma unroll
        for (int j = 0; j < 12; ++j)
            acc[i][j] = 0.f;

    #pragma unroll 4
    for (int d = 0; d < HD_; ++d) {
        float a[4], bb[12];
        #pragma unroll
        for (int i = 0; i < 4; ++i)
            a[i] = sQT[d * SQT_STRIDE + q0 + i];
        #pragma unroll
        for (int j = 0; j < 12; ++j)
            bb[j] = sKT[d * SKT_STRIDE + tx + 16 * j];
        #pragma unroll
        for (int i = 0; i < 4; ++i)
            #pragma unroll
            for (int j = 0; j < 12; ++j)
                acc[i][j] = fmaf(a[i], bb[j], acc[i][j]);
    }

    // ---- Softmax per query row. Row i (local query qi) is valid for
    // key rows r in [qi, qi+126] (band mask == reference mask). The 16
    // threads sharing a row are lanes {(ty&1)*16 + tx}; xor-shuffles with
    // masks 8..1 reduce within that 16-lane group.
    float inv[4];
    #pragma unroll
    for (int i = 0; i < 4; ++i) {
        const int qi = q0 + i;
        float m = -FLT_MAX;
        #pragma unroll
        for (int j = 0; j < 12; ++j) {
            int nn = tx + 16 * j;
            bool valid = (nn >= qi) && (nn <= qi + 2 * W_);
            float vsc = valid ? acc[i][j] : -FLT_MAX;
            acc[i][j] = vsc;
            m = fmaxf(m, vsc);
        }
        #pragma unroll
        for (int o = 8; o >= 1; o >>= 1)
            m = fmaxf(m, __shfl_xor_sync(0xffffffffu, m, o));

        float ssum = 0.f;
        #pragma unroll
        for (int j = 0; j < 12; ++j) {
            int nn = tx + 16 * j;
            bool valid = (nn >= qi) && (nn <= qi + 2 * W_);
            float p = valid ? __expf(acc[i][j] - m) : 0.f;
            acc[i][j] = p;
            ssum += p;
        }
        #pragma unroll
        for (int o = 8; o >= 1; o >>= 1)
            ssum += __shfl_xor_sync(0xffffffffu, ssum, o);
        inv[i] = 1.0f / ssum;

        // Store unnormalized P transposed: [r][q]. Stride 65 → lanes with
        // varying tx hit distinct banks (2-way from the two ty-halves).
        #pragma unroll
        for (int j = 0; j < 12; ++j)
            sPT[(tx + 16 * j) * SPT_STRIDE + qi] = acc[i][j];
    }
    __syncthreads();

    // ---- GEMM2: O[64][64] = P @ V, reduction over r = 0..191 (rows with
    // p==0 or zero V contribute nothing). Thread tile 4q x 4d, d = tx+16*j.
    float oacc[4][4];
    #pragma unroll
    for (int i = 0; i < 4; ++i)
        #pragma unroll
        for (int j = 0; j < 4; ++j)
            oacc[i][j] = 0.f;

    #pragma unroll 4
    for (int r = 0; r < NK; ++r) {
        float a[4], bb[4];
        #pragma unroll
        for (int i = 0; i < 4; ++i)
            a[i] = sPT[r * SPT_STRIDE + q0 + i];
        #pragma unroll
        for (int j = 0; j < 4; ++j)
            bb[j] = sV[r * SV_STRIDE + tx + 16 * j];
        #pragma unroll
        for (int i = 0; i < 4; ++i)
            #pragma unroll
            for (int j = 0; j < 4; ++j)
                oacc[i][j] = fmaf(a[i], bb[j], oacc[i][j]);
    }

    // ---- Epilogue: normalize by 1/sum and store valid queries only.
    #pragma unroll
    for (int i = 0; i < 4; ++i) {
        int t = t0 + q0 + i;
        if (t < S_) {
            float sc = inv[i];
            size_t base = ((size_t)(batch * S_ + t) * NH_ + head) * HD_;
            #pragma unroll
            for (int j = 0; j < 4; ++j)
                og[base + tx + 16 * j] = oacc[i][j] * sc;
        }
    }
}

extern "C" void kernel_launch(void* const* d_in, const int* in_sizes, int n_in,
                              void* d_out, int out_size)
{
    const float* q = (const float*)d_in[0];
    const float* k = (const float*)d_in[1];
    const float* v = (const float*)d_in[2];
    float* o = (float*)d_out;

    // Idempotent, called every launch (no static guards).
    cudaFuncSetAttribute(window_attn_kernel,
                         cudaFuncAttributeMaxDynamicSharedMemorySize,
                         SMEM_FLOATS * (int)sizeof(float));

    window_attn_kernel<<<B_ * NH_ * NCHUNK, 256,
                         SMEM_FLOATS * (int)sizeof(float)>>>(q, k, v, o);
}

// round 5
// speedup vs baseline: 1.5501x; 1.5501x over previous
#include <cuda_runtime.h>
#include <cstdint>
#include <cstddef>

// ---------------- problem constants ----------------
#define B_      8
#define S_      4094
#define NH_     8
#define HD_     64
#define TQ      128        // queries per CTA (M)
#define NKEY    256        // padded key rows per CTA (254 real + 2 always-masked)
#define NCHUNK  32         // ceil(4094/128)

// ---------------- smem layout (float units) ----------------
#define QSTR 68            // [128][68]  bank-conflict-free A-fragment loads
#define KSTR 68            // [256][68]  conflict-free B-fragment loads (GEMM1)
#define VSTR 72            // [256][72]  conflict-free B-fragment loads (GEMM2)
#define PSTR 68            // per-warp P buffer [32][68]

#define OFF_Q 0
#define OFF_K (TQ * QSTR)                 // 8704
#define OFF_V (OFF_K + NKEY * KSTR)       // 26112
#define OFF_P (OFF_V + NKEY * VSTR)       // 44544
#define PW    (32 * PSTR)                 // 2176 floats per warp
#define SMEM_FLOATS (OFF_P + 4 * PW)      // 53248 floats = 212992 B

// ---------------- helpers ----------------
__device__ __forceinline__ float to_tf32(float x) {
    uint32_t u;
    asm("cvt.rna.tf32.f32 %0, %1;" : "=r"(u) : "f"(x));
    return __uint_as_float(u);
}
__device__ __forceinline__ uint32_t fb(float x) { return __float_as_uint(x); }

// m16n8k8 tf32 mma, fp32 accumulate (family-portable, sm_80+)
__device__ __forceinline__ void mma8(float* d, const uint32_t* a, const uint32_t* b) {
    asm volatile(
        "mma.sync.aligned.m16n8k8.row.col.f32.tf32.tf32.f32 "
        "{%0,%1,%2,%3}, {%4,%5,%6,%7}, {%8,%9}, {%0,%1,%2,%3};"
        : "+f"(d[0]), "+f"(d[1]), "+f"(d[2]), "+f"(d[3])
        : "r"(a[0]), "r"(a[1]), "r"(a[2]), "r"(a[3]), "r"(b[0]), "r"(b[1]));
}

// ---------------- kernel ----------------
__global__ __launch_bounds__(128, 1)
void window_attn_mma(const float* __restrict__ qg, const float* __restrict__ kg,
                     const float* __restrict__ vg, float* __restrict__ og)
{
    extern __shared__ float sm[];
    float* sQ = sm + OFF_Q;
    float* sK = sm + OFF_K;
    float* sV = sm + OFF_V;

    const int bx    = blockIdx.x;
    const int chunk = bx & (NCHUNK - 1);
    const int head  = (bx >> 5) & (NH_ - 1);
    const int batch = bx >> 8;
    const int t0    = chunk * TQ;

    const int tid  = threadIdx.x;
    const int w    = tid >> 5;
    const int lane = tid & 31;
    const int lr   = lane >> 2;   // row-in-fragment
    const int lc   = lane & 3;    // col-in-fragment

    // ---- fill Q (pre-scaled by 1/8, tf32-rounded). float4 traffic.
    for (int idx = tid; idx < TQ * 16; idx += 128) {
        int row = idx >> 4, c4 = idx & 15;
        int t = t0 + row;
        float4 v = make_float4(0.f, 0.f, 0.f, 0.f);
        if (t < S_) {
            v = reinterpret_cast<const float4*>(
                    qg + (((size_t)batch * S_ + t) * NH_ + head) * HD_)[c4];
            v.x = to_tf32(v.x * 0.125f); v.y = to_tf32(v.y * 0.125f);
            v.z = to_tf32(v.z * 0.125f); v.w = to_tf32(v.w * 0.125f);
        }
        reinterpret_cast<float4*>(sQ + row * QSTR)[c4] = v;
    }
    // ---- fill K and V; out-of-sequence rows ZERO (reference's zero padding).
    for (int idx = tid; idx < NKEY * 16; idx += 128) {
        int row = idx >> 4, c4 = idx & 15;
        int g = t0 - 63 + row;
        float4 kv = make_float4(0.f, 0.f, 0.f, 0.f);
        float4 vv = make_float4(0.f, 0.f, 0.f, 0.f);
        if (g >= 0 && g < S_) {
            size_t base = (((size_t)batch * S_ + g) * NH_ + head) * HD_;
            kv = reinterpret_cast<const float4*>(kg + base)[c4];
            vv = reinterpret_cast<const float4*>(vg + base)[c4];
            kv.x = to_tf32(kv.x); kv.y = to_tf32(kv.y);
            kv.z = to_tf32(kv.z); kv.w = to_tf32(kv.w);
            vv.x = to_tf32(vv.x); vv.y = to_tf32(vv.y);
            vv.z = to_tf32(vv.z); vv.w = to_tf32(vv.w);
        }
        reinterpret_cast<float4*>(sK + row * KSTR)[c4] = kv;
        reinterpret_cast<float4*>(sV + row * VSTR)[c4] = vv;
    }
    __syncthreads();

    float* sP = sm + OFF_P + w * PW;      // per-warp P buffer [32][PSTR]
    const int qbase = w * 32;             // this warp's first query row

    float Oacc[2][8][4];
    #pragma unroll
    for (int mt = 0; mt < 2; ++mt)
        #pragma unroll
        for (int nt = 0; nt < 8; ++nt)
            #pragma unroll
            for (int e = 0; e < 4; ++e) Oacc[mt][nt][e] = 0.f;
    float psum[2][2] = {{0.f, 0.f}, {0.f, 0.f}};

    #pragma unroll
    for (int c = 0; c < 4; ++c) {
        const int kc0 = c * 64;

        // ---- GEMM1 chunk: S[32 x 64] = Q_warp @ K_chunk^T
        float Sacc[2][8][4];
        #pragma unroll
        for (int mt = 0; mt < 2; ++mt)
            #pragma unroll
            for (int nt = 0; nt < 8; ++nt)
                #pragma unroll
                for (int e = 0; e < 4; ++e) Sacc[mt][nt][e] = 0.f;

        #pragma unroll
        for (int kk = 0; kk < 8; ++kk) {
            uint32_t afr[2][4];
            #pragma unroll
            for (int mt = 0; mt < 2; ++mt) {
                const float* qp = sQ + (qbase + 16 * mt + lr) * QSTR + kk * 8 + lc;
                afr[mt][0] = fb(qp[0]);
                afr[mt][1] = fb(qp[8 * QSTR]);
                afr[mt][2] = fb(qp[4]);
                afr[mt][3] = fb(qp[8 * QSTR + 4]);
            }
            #pragma unroll
            for (int nt = 0; nt < 8; ++nt) {
                const float* kp = sK + (kc0 + nt * 8 + lr) * KSTR + kk * 8 + lc;
                uint32_t bfr[2] = { fb(kp[0]), fb(kp[4]) };
                mma8(Sacc[0][nt], afr[0], bfr);
                mma8(Sacc[1][nt], afr[1], bfr);
            }
        }

        // ---- band mask + exp + row-sum partials; P chunk -> smem (tf32)
        __syncwarp();   // previous chunk's GEMM2 reads of sP are done
        #pragma unroll
        for (int mt = 0; mt < 2; ++mt)
            #pragma unroll
            for (int h = 0; h < 2; ++h) {
                const int m = qbase + 16 * mt + lr + 8 * h;  // local query idx
                #pragma unroll
                for (int nt = 0; nt < 8; ++nt) {
                    const int j0 = kc0 + nt * 8 + 2 * lc;    // key window idx
                    float s0 = Sacc[mt][nt][2 * h + 0];
                    float s1 = Sacc[mt][nt][2 * h + 1];
                    float p0 = (j0     >= m && j0     <= m + 126) ? __expf(s0) : 0.f;
                    float p1 = (j0 + 1 >= m && j0 + 1 <= m + 126) ? __expf(s1) : 0.f;
                    psum[mt][h] += p0 + p1;
                    float2 pv = make_float2(to_tf32(p0), to_tf32(p1));
                    *reinterpret_cast<float2*>(
                        sP + (16 * mt + lr + 8 * h) * PSTR + nt * 8 + 2 * lc) = pv;
                }
            }
        __syncwarp();

        // ---- GEMM2 partial: O[32 x 64] += P_chunk @ V_chunk
        #pragma unroll
        for (int kk = 0; kk < 8; ++kk) {
            uint32_t afr[2][4];
            #pragma unroll
            for (int mt = 0; mt < 2; ++mt) {
                const float* pp = sP + (16 * mt + lr) * PSTR + kk * 8 + lc;
                afr[mt][0] = fb(pp[0]);
                afr[mt][1] = fb(pp[8 * PSTR]);
                afr[mt][2] = fb(pp[4]);
                afr[mt][3] = fb(pp[8 * PSTR + 4]);
            }
            #pragma unroll
            for (int nt = 0; nt < 8; ++nt) {
                const float* vp = sV + (kc0 + kk * 8 + lc) * VSTR + nt * 8 + lr;
                uint32_t bfr[2] = { fb(vp[0]), fb(vp[4 * VSTR]) };
                mma8(Oacc[0][nt], afr[0], bfr);
                mma8(Oacc[1][nt], afr[1], bfr);
            }
        }
    }

    // ---- row sums: reduce across the 4 lanes of each quad
    #pragma unroll
    for (int mt = 0; mt < 2; ++mt)
        #pragma unroll
        for (int h = 0; h < 2; ++h) {
            float s = psum[mt][h];
            s += __shfl_xor_sync(0xffffffffu, s, 1);
            s += __shfl_xor_sync(0xffffffffu, s, 2);
            psum[mt][h] = s;
        }

    // ---- epilogue: normalize and store (float2, coalesced-ish)
    #pragma unroll
    for (int mt = 0; mt < 2; ++mt)
        #pragma unroll
        for (int h = 0; h < 2; ++h) {
            const int m = qbase + 16 * mt + lr + 8 * h;
            const int t = t0 + m;
            if (t < S_) {
                const float inv = 1.0f / psum[mt][h];
                float* dst = og + (((size_t)batch * S_ + t) * NH_ + head) * HD_;
                #pragma unroll
                for (int nt = 0; nt < 8; ++nt) {
                    float2 o;
                    o.x = Oacc[mt][nt][2 * h + 0] * inv;
                    o.y = Oacc[mt][nt][2 * h + 1] * inv;
                    *reinterpret_cast<float2*>(dst + nt * 8 + 2 * lc) = o;
                }
            }
        }
}

extern "C" void kernel_launch(void* const* d_in, const int* in_sizes, int n_in,
                              void* d_out, int out_size)
{
    const float* q = (const float*)d_in[0];
    const float* k = (const float*)d_in[1];
    const float* v = (const float*)d_in[2];
    float* o = (float*)d_out;

    cudaFuncSetAttribute(window_attn_mma,
                         cudaFuncAttributeMaxDynamicSharedMemorySize,
                         SMEM_FLOATS * (int)sizeof(float));

    window_attn_mma<<<B_ * NH_ * NCHUNK, 128, SMEM_FLOATS * (int)sizeof(float)>>>(q, k, v, o);
}

// round 7
// speedup vs baseline: 2.2884x; 1.4763x over previous
#include <cuda_runtime.h>
#include <cstdint>
#include <cstddef>

// ---------------- problem constants ----------------
#define B_      8
#define S_      4094
#define NH_     8
#define HD_     64
#define TQ      128        // queries per CTA (M)
#define NKEY    256        // padded key rows per CTA (254 real + 2 always-masked)
#define NCHUNK  32         // ceil(4094/128)
#define NW      8          // warps per CTA
#define QPW     16         // query rows per warp

// ---------------- smem layout (float units) ----------------
#define QSTR 68            // [128][68]  bank-conflict-free A-fragment loads
#define KSTR 68            // [256][68]  conflict-free B-fragment loads (GEMM1)
#define VSTR 72            // [256][72]  conflict-free B-fragment loads (GEMM2)
#define PSTR 68            // per-warp P buffer [16][68]

#define OFF_Q 0
#define OFF_K (TQ * QSTR)                 // 8704
#define OFF_V (OFF_K + NKEY * KSTR)       // 26112
#define OFF_P (OFF_V + NKEY * VSTR)       // 44544
#define PW    (QPW * PSTR)                // 1088 floats per warp
#define SMEM_FLOATS (OFF_P + NW * PW)     // 53248 floats = 212992 B

// ---------------- helpers ----------------
__device__ __forceinline__ float to_tf32(float x) {
    uint32_t u;
    asm("cvt.rna.tf32.f32 %0, %1;" : "=r"(u) : "f"(x));
    return __uint_as_float(u);
}
__device__ __forceinline__ uint32_t fb(float x) { return __float_as_uint(x); }

// m16n8k8 tf32 mma, fp32 accumulate (family-portable, sm_80+)
__device__ __forceinline__ void mma8(float* d, const uint32_t* a, const uint32_t* b) {
    asm volatile(
        "mma.sync.aligned.m16n8k8.row.col.f32.tf32.tf32.f32 "
        "{%0,%1,%2,%3}, {%4,%5,%6,%7}, {%8,%9}, {%0,%1,%2,%3};"
        : "+f"(d[0]), "+f"(d[1]), "+f"(d[2]), "+f"(d[3])
        : "r"(a[0]), "r"(a[1]), "r"(a[2]), "r"(a[3]), "r"(b[0]), "r"(b[1]));
}

// ---------------- kernel ----------------
__global__ __launch_bounds__(256, 1)
void window_attn_mma(const float* __restrict__ qg, const float* __restrict__ kg,
                     const float* __restrict__ vg, float* __restrict__ og)
{
    extern __shared__ float sm[];
    float* sQ = sm + OFF_Q;
    float* sK = sm + OFF_K;
    float* sV = sm + OFF_V;

    const int bx    = blockIdx.x;
    const int chunk = bx & (NCHUNK - 1);
    const int head  = (bx >> 5) & (NH_ - 1);
    const int batch = bx >> 8;
    const int t0    = chunk * TQ;

    const int tid  = threadIdx.x;
    const int w    = tid >> 5;
    const int lane = tid & 31;
    const int lr   = lane >> 2;   // row-in-fragment
    const int lc   = lane & 3;    // col-in-fragment

    // ---- fill Q (pre-scaled by 1/8, tf32-rounded). float4 traffic.
    for (int idx = tid; idx < TQ * 16; idx += 256) {
        int row = idx >> 4, c4 = idx & 15;
        int t = t0 + row;
        float4 v = make_float4(0.f, 0.f, 0.f, 0.f);
        if (t < S_) {
            v = reinterpret_cast<const float4*>(
                    qg + (((size_t)batch * S_ + t) * NH_ + head) * HD_)[c4];
            v.x = to_tf32(v.x * 0.125f); v.y = to_tf32(v.y * 0.125f);
            v.z = to_tf32(v.z * 0.125f); v.w = to_tf32(v.w * 0.125f);
        }
        reinterpret_cast<float4*>(sQ + row * QSTR)[c4] = v;
    }
    // ---- fill K and V; out-of-sequence rows ZERO (reference's zero padding).
    for (int idx = tid; idx < NKEY * 16; idx += 256) {
        int row = idx >> 4, c4 = idx & 15;
        int g = t0 - 63 + row;
        float4 kv = make_float4(0.f, 0.f, 0.f, 0.f);
        float4 vv = make_float4(0.f, 0.f, 0.f, 0.f);
        if (g >= 0 && g < S_) {
            size_t base = (((size_t)batch * S_ + g) * NH_ + head) * HD_;
            kv = reinterpret_cast<const float4*>(kg + base)[c4];
            vv = reinterpret_cast<const float4*>(vg + base)[c4];
            kv.x = to_tf32(kv.x); kv.y = to_tf32(kv.y);
            kv.z = to_tf32(kv.z); kv.w = to_tf32(kv.w);
            vv.x = to_tf32(vv.x); vv.y = to_tf32(vv.y);
            vv.z = to_tf32(vv.z); vv.w = to_tf32(vv.w);
        }
        reinterpret_cast<float4*>(sK + row * KSTR)[c4] = kv;
        reinterpret_cast<float4*>(sV + row * VSTR)[c4] = vv;
    }
    __syncthreads();

    float* sP = sm + OFF_P + w * PW;      // per-warp P buffer [16][PSTR]
    const int qbase = w * QPW;            // this warp's first query row

    float Oacc[8][4];
    #pragma unroll
    for (int nt = 0; nt < 8; ++nt)
        #pragma unroll
        for (int e = 0; e < 4; ++e) Oacc[nt][e] = 0.f;
    float psum[2] = {0.f, 0.f};

    #pragma unroll
    for (int c = 0; c < 4; ++c) {
        const int kc0 = c * 64;

        // ---- GEMM1 chunk: S[16 x 64] = Q_warp @ K_chunk^T
        float Sacc[8][4];
        #pragma unroll
        for (int nt = 0; nt < 8; ++nt)
            #pragma unroll
            for (int e = 0; e < 4; ++e) Sacc[nt][e] = 0.f;

        #pragma unroll
        for (int kk = 0; kk < 8; ++kk) {
            uint32_t afr[4];
            {
                const float* qp = sQ + (qbase + lr) * QSTR + kk * 8 + lc;
                afr[0] = fb(qp[0]);
                afr[1] = fb(qp[8 * QSTR]);
                afr[2] = fb(qp[4]);
                afr[3] = fb(qp[8 * QSTR + 4]);
            }
            #pragma unroll
            for (int nt = 0; nt < 8; ++nt) {
                const float* kp = sK + (kc0 + nt * 8 + lr) * KSTR + kk * 8 + lc;
                uint32_t bfr[2] = { fb(kp[0]), fb(kp[4]) };
                mma8(Sacc[nt], afr, bfr);
            }
        }

        // ---- band mask + exp + row-sum partials; P chunk -> smem (tf32)
        __syncwarp();   // previous chunk's GEMM2 reads of sP are done
        #pragma unroll
        for (int h = 0; h < 2; ++h) {
            const int m = qbase + lr + 8 * h;            // local query idx
            #pragma unroll
            for (int nt = 0; nt < 8; ++nt) {
                const int j0 = kc0 + nt * 8 + 2 * lc;    // key window idx
                float s0 = Sacc[nt][2 * h + 0];
                float s1 = Sacc[nt][2 * h + 1];
                float p0 = (j0     >= m && j0     <= m + 126) ? __expf(s0) : 0.f;
                float p1 = (j0 + 1 >= m && j0 + 1 <= m + 126) ? __expf(s1) : 0.f;
                psum[h] += p0 + p1;
                float2 pv = make_float2(to_tf32(p0), to_tf32(p1));
                *reinterpret_cast<float2*>(
                    sP + (lr + 8 * h) * PSTR + nt * 8 + 2 * lc) = pv;
            }
        }
        __syncwarp();

        // ---- GEMM2 partial: O[16 x 64] += P_chunk @ V_chunk
        #pragma unroll
        for (int kk = 0; kk < 8; ++kk) {
            uint32_t afr[4];
            {
                const float* pp = sP + lr * PSTR + kk * 8 + lc;
                afr[0] = fb(pp[0]);
                afr[1] = fb(pp[8 * PSTR]);
                afr[2] = fb(pp[4]);
                afr[3] = fb(pp[8 * PSTR + 4]);
            }
            #pragma unroll
            for (int nt = 0; nt < 8; ++nt) {
                const float* vp = sV + (kc0 + kk * 8 + lc) * VSTR + nt * 8 + lr;
                uint32_t bfr[2] = { fb(vp[0]), fb(vp[4 * VSTR]) };
                mma8(Oacc[nt], afr, bfr);
            }
        }
    }

    // ---- row sums: reduce across the 4 lanes of each quad
    #pragma unroll
    for (int h = 0; h < 2; ++h) {
        float s = psum[h];
        s += __shfl_xor_sync(0xffffffffu, s, 1);
        s += __shfl_xor_sync(0xffffffffu, s, 2);
        psum[h] = s;
    }

    // ---- epilogue: normalize and store
    #pragma unroll
    for (int h = 0; h < 2; ++h) {
        const int m = qbase + lr + 8 * h;
        const int t = t0 + m;
        if (t < S_) {
            const float inv = 1.0f / psum[h];
            float* dst = og + (((size_t)batch * S_ + t) * NH_ + head) * HD_;
            #pragma unroll
            for (int nt = 0; nt < 8; ++nt) {
                float2 o;
                o.x = Oacc[nt][2 * h + 0] * inv;
                o.y = Oacc[nt][2 * h + 1] * inv;
                *reinterpret_cast<float2*>(dst + nt * 8 + 2 * lc) = o;
            }
        }
    }
}

extern "C" void kernel_launch(void* const* d_in, const int* in_sizes, int n_in,
                              void* d_out, int out_size)
{
    const float* q = (const float*)d_in[0];
    const float* k = (const float*)d_in[1];
    const float* v = (const float*)d_in[2];
    float* o = (float*)d_out;

    (void)cudaFuncSetAttribute(window_attn_mma,
                               cudaFuncAttributeMaxDynamicSharedMemorySize,
                               SMEM_FLOATS * (int)sizeof(float));

    window_attn_mma<<<B_ * NH_ * NCHUNK, 256, SMEM_FLOATS * (int)sizeof(float)>>>(q, k, v, o);
}

// round 9
// speedup vs baseline: 3.1216x; 1.3641x over previous
#include <cuda_runtime.h>
#include <cstdint>
#include <cstddef>

// ---------------- problem constants ----------------
#define B_      8
#define S_      4094
#define NH_     8
#define HD_     64
#define TQ      128        // queries per CTA (M)
#define NKEY    256        // padded key rows per CTA (254 real + 2 always-masked)
#define NCHUNK  32         // ceil(4094/128)
#define NW      16         // warps per CTA (8 query groups x 2 key halves)
#define QPW     16         // query rows per warp

// ---------------- smem layout (float units) ----------------
#define QSTR 68            // [128][68]  bank-conflict-free A-fragment loads
#define KSTR 68            // [256][68]  conflict-free B-fragment loads (GEMM1)
#define VSTR 72            // [256][72]  conflict-free B-fragment loads (GEMM2)
#define OSTR 68            // staging for cross-half O reduction [16][68] per pair

#define OFF_Q  0
#define OFF_K  (TQ * QSTR)                 // 8704
#define OFF_V  (OFF_K + NKEY * KSTR)       // 26112
#define OFF_O  (OFF_V + NKEY * VSTR)       // 44544
#define OPW    (QPW * OSTR)                // 1088 floats per pair
#define OFF_PS (OFF_O + 8 * OPW)           // 53248
#define SMEM_FLOATS (OFF_PS + 8 * QPW)     // 53376 floats = 213504 B

// ---------------- helpers ----------------
__device__ __forceinline__ float to_tf32(float x) {
    uint32_t u;
    asm("cvt.rna.tf32.f32 %0, %1;" : "=r"(u) : "f"(x));
    return __uint_as_float(u);
}
__device__ __forceinline__ uint32_t fb(float x) { return __float_as_uint(x); }

// m16n8k8 tf32 mma, fp32 accumulate (family-portable, sm_80+)
__device__ __forceinline__ void mma8(float* d, const uint32_t* a, const uint32_t* b) {
    asm volatile(
        "mma.sync.aligned.m16n8k8.row.col.f32.tf32.tf32.f32 "
        "{%0,%1,%2,%3}, {%4,%5,%6,%7}, {%8,%9}, {%0,%1,%2,%3};"
        : "+f"(d[0]), "+f"(d[1]), "+f"(d[2]), "+f"(d[3])
        : "r"(a[0]), "r"(a[1]), "r"(a[2]), "r"(a[3]), "r"(b[0]), "r"(b[1]));
}

// ---------------- kernel ----------------
__global__ __launch_bounds__(512, 1)
void window_attn_mma(const float* __restrict__ qg, const float* __restrict__ kg,
                     const float* __restrict__ vg, float* __restrict__ og)
{
    extern __shared__ float sm[];
    float* sQ  = sm + OFF_Q;
    float* sK  = sm + OFF_K;
    float* sV  = sm + OFF_V;
    float* sPS = sm + OFF_PS;

    const int bx    = blockIdx.x;
    const int chunk = bx & (NCHUNK - 1);
    const int head  = (bx >> 5) & (NH_ - 1);
    const int batch = bx >> 8;
    const int t0    = chunk * TQ;

    const int tid  = threadIdx.x;
    const int w    = tid >> 5;
    const int lane = tid & 31;
    const int lr   = lane >> 2;   // row-in-fragment
    const int lc   = lane & 3;    // col-in-fragment
    const int wq   = w & 7;       // query group (16 rows)
    const int kh   = w >> 3;      // key half (128 keys)

    // ---- fill Q (pre-scaled by 1/8, tf32-rounded). float4 traffic.
    for (int idx = tid; idx < TQ * 16; idx += 512) {
        int row = idx >> 4, c4 = idx & 15;
        int t = t0 + row;
        float4 v = make_float4(0.f, 0.f, 0.f, 0.f);
        if (t < S_) {
            v = reinterpret_cast<const float4*>(
                    qg + (((size_t)batch * S_ + t) * NH_ + head) * HD_)[c4];
            v.x = to_tf32(v.x * 0.125f); v.y = to_tf32(v.y * 0.125f);
            v.z = to_tf32(v.z * 0.125f); v.w = to_tf32(v.w * 0.125f);
        }
        reinterpret_cast<float4*>(sQ + row * QSTR)[c4] = v;
    }
    // ---- fill K and V; out-of-sequence rows ZERO (reference's zero padding).
    for (int idx = tid; idx < NKEY * 16; idx += 512) {
        int row = idx >> 4, c4 = idx & 15;
        int g = t0 - 63 + row;
        float4 kv = make_float4(0.f, 0.f, 0.f, 0.f);
        float4 vv = make_float4(0.f, 0.f, 0.f, 0.f);
        if (g >= 0 && g < S_) {
            size_t base = (((size_t)batch * S_ + g) * NH_ + head) * HD_;
            kv = reinterpret_cast<const float4*>(kg + base)[c4];
            vv = reinterpret_cast<const float4*>(vg + base)[c4];
            kv.x = to_tf32(kv.x); kv.y = to_tf32(kv.y);
            kv.z = to_tf32(kv.z); kv.w = to_tf32(kv.w);
            vv.x = to_tf32(vv.x); vv.y = to_tf32(vv.y);
            vv.z = to_tf32(vv.z); vv.w = to_tf32(vv.w);
        }
        reinterpret_cast<float4*>(sK + row * KSTR)[c4] = kv;
        reinterpret_cast<float4*>(sV + row * VSTR)[c4] = vv;
    }
    __syncthreads();

    const int qbase = wq * QPW;          // this warp's first query row
    const int srcA  = (lr << 2) + (lc >> 1);   // quad shuffle sources
    const int srcB  = srcA + 2;
    const bool odd  = lc & 1;

    float Oacc[8][4];
    #pragma unroll
    for (int nt = 0; nt < 8; ++nt)
        #pragma unroll
        for (int e = 0; e < 4; ++e) Oacc[nt][e] = 0.f;
    float psum[2] = {0.f, 0.f};

    #pragma unroll
    for (int c = 0; c < 2; ++c) {
        const int kc0 = kh * 128 + c * 64;   // this warp's key chunk

        // ---- GEMM1 chunk: S[16 x 64] = Q_warp @ K_chunk^T
        float Sacc[8][4];
        #pragma unroll
        for (int nt = 0; nt < 8; ++nt)
            #pragma unroll
            for (int e = 0; e < 4; ++e) Sacc[nt][e] = 0.f;

        #pragma unroll
        for (int kk = 0; kk < 8; ++kk) {
            uint32_t afr[4];
            {
                const float* qp = sQ + (qbase + lr) * QSTR + kk * 8 + lc;
                afr[0] = fb(qp[0]);
                afr[1] = fb(qp[8 * QSTR]);
                afr[2] = fb(qp[4]);
                afr[3] = fb(qp[8 * QSTR + 4]);
            }
            #pragma unroll
            for (int nt = 0; nt < 8; ++nt) {
                const float* kp = sK + (kc0 + nt * 8 + lr) * KSTR + kk * 8 + lc;
                uint32_t bfr[2] = { fb(kp[0]), fb(kp[4]) };
                mma8(Sacc[nt], afr, bfr);
            }
        }

        // ---- band mask + exp (tf32-rounded) + row-sum partials, in registers
        #pragma unroll
        for (int h = 0; h < 2; ++h) {
            const int m = qbase + lr + 8 * h;            // local query idx
            #pragma unroll
            for (int nt = 0; nt < 8; ++nt) {
                const int j0 = kc0 + nt * 8 + 2 * lc;    // key window idx
                float s0 = Sacc[nt][2 * h + 0];
                float s1 = Sacc[nt][2 * h + 1];
                float p0 = (j0     >= m && j0     <= m + 126) ? __expf(s0) : 0.f;
                float p1 = (j0 + 1 >= m && j0 + 1 <= m + 126) ? __expf(s1) : 0.f;
                psum[h] += p0 + p1;
                Sacc[nt][2 * h + 0] = to_tf32(p0);
                Sacc[nt][2 * h + 1] = to_tf32(p1);
            }
        }

        // ---- GEMM2 partial: O[16 x 64] += P_chunk @ V_chunk.
        // A-fragment built from D-fragment P via intra-warp shuffles:
        //  a0=P[lr][8k+lc]  a1=P[lr+8][8k+lc]  a2=P[lr][8k+lc+4]  a3=P[lr+8][8k+lc+4]
        #pragma unroll
        for (int kk = 0; kk < 8; ++kk) {
            float q0 = __shfl_sync(0xffffffffu, Sacc[kk][0], srcA);
            float q1 = __shfl_sync(0xffffffffu, Sacc[kk][1], srcA);
            float q2 = __shfl_sync(0xffffffffu, Sacc[kk][2], srcA);
            float q3 = __shfl_sync(0xffffffffu, Sacc[kk][3], srcA);
            float r0 = __shfl_sync(0xffffffffu, Sacc[kk][0], srcB);
            float r1 = __shfl_sync(0xffffffffu, Sacc[kk][1], srcB);
            float r2 = __shfl_sync(0xffffffffu, Sacc[kk][2], srcB);
            float r3 = __shfl_sync(0xffffffffu, Sacc[kk][3], srcB);
            uint32_t afr[4];
            afr[0] = fb(odd ? q1 : q0);
            afr[1] = fb(odd ? q3 : q2);
            afr[2] = fb(odd ? r1 : r0);
            afr[3] = fb(odd ? r3 : r2);
            #pragma unroll
            for (int nt = 0; nt < 8; ++nt) {
                const float* vp = sV + (kc0 + kk * 8 + lc) * VSTR + nt * 8 + lr;
                uint32_t bfr[2] = { fb(vp[0]), fb(vp[4 * VSTR]) };
                mma8(Oacc[nt], afr, bfr);
            }
        }
    }

    // ---- row-sum partials: reduce across the 4 lanes of each quad
    #pragma unroll
    for (int h = 0; h < 2; ++h) {
        float s = psum[h];
        s += __shfl_xor_sync(0xffffffffu, s, 1);
        s += __shfl_xor_sync(0xffffffffu, s, 2);
        psum[h] = s;
    }

    // ---- cross-half combine: key-half-1 warps stage raw O + psum in smem
    __syncthreads();
    if (kh == 1) {
        float* so = sm + OFF_O + wq * OPW;
        #pragma unroll
        for (int h = 0; h < 2; ++h) {
            #pragma unroll
            for (int nt = 0; nt < 8; ++nt) {
                float2 o;
                o.x = Oacc[nt][2 * h + 0];
                o.y = Oacc[nt][2 * h + 1];
                *reinterpret_cast<float2*>(so + (lr + 8 * h) * OSTR + nt * 8 + 2 * lc) = o;
            }
            if (lc == 0) sPS[wq * QPW + lr + 8 * h] = psum[h];
        }
    }
    __syncthreads();

    // ---- key-half-0 warps add the staged half, normalize, store
    if (kh == 0) {
        const float* so = sm + OFF_O + wq * OPW;
        #pragma unroll
        for (int h = 0; h < 2; ++h) {
            const int m = qbase + lr + 8 * h;
            const int t = t0 + m;
            if (t < S_) {
                const float inv = 1.0f / (psum[h] + sPS[wq * QPW + lr + 8 * h]);
                float* dst = og + (((size_t)batch * S_ + t) * NH_ + head) * HD_;
                #pragma unroll
                for (int nt = 0; nt < 8; ++nt) {
                    float2 s2 = *reinterpret_cast<const float2*>(
                        so + (lr + 8 * h) * OSTR + nt * 8 + 2 * lc);
                    float2 o;
                    o.x = (Oacc[nt][2 * h + 0] + s2.x) * inv;
                    o.y = (Oacc[nt][2 * h + 1] + s2.y) * inv;
                    *reinterpret_cast<float2*>(dst + nt * 8 + 2 * lc) = o;
                }
            }
        }
    }
}

extern "C" void kernel_launch(void* const* d_in, const int* in_sizes, int n_in,
                              void* d_out, int out_size)
{
    const float* q = (const float*)d_in[0];
    const float* k = (const float*)d_in[1];
    const float* v = (const float*)d_in[2];
    float* o = (float*)d_out;

    (void)cudaFuncSetAttribute(window_attn_mma,
                               cudaFuncAttributeMaxDynamicSharedMemorySize,
                               SMEM_FLOATS * (int)sizeof(float));

    window_attn_mma<<<B_ * NH_ * NCHUNK, 512, SMEM_FLOATS * (int)sizeof(float)>>>(q, k, v, o);
}